// round 7
// baseline (speedup 1.0000x reference)
#include <cuda_runtime.h>
#include <cuda_bf16.h>
#include <cstdint>

#define LL 65536
#define DD 256
#define CC 1024     // number of chunks
#define RR 64       // rows per chunk
#define NSEG 32     // segments
#define SEGC 32     // chunks per segment (CC / NSEG)

#define NEG_INF __int_as_float(0xff800000)

// ---- scratch (device globals) ----
__device__ float g_s[LL];            // s[i] = K[i]·q
__device__ float g_M[CC], g_U[CC];   // per-chunk aggregates (U ref M)
__device__ float g_W[CC * DD];       // per-chunk vector aggregate (ref M_c)
__device__ float g_Mp[CC], g_Up[CC]; // exclusive prefix (Up ref Mp)
__device__ float g_Wp[CC * DD];      // segment-local exclusive W prefix (ref Mp_c)
__device__ float g_seg[NSEG * DD];   // segment aggregates (ref Mp[(b+1)*SEGC])

__device__ __forceinline__ void l2_prefetch(const void* p) {
    asm volatile("prefetch.global.L2 [%0];" :: "l"(p));
}

// ============================================================
// Pass 1: s = K·q ; per-chunk (M, U, W) reduction.
// V tile L2-prefetched up front to overlap with the K-dot phase.
// ============================================================
__global__ __launch_bounds__(256, 8) void k_pass1(const float* __restrict__ K,
                                                  const float* __restrict__ V,
                                                  const float* __restrict__ q) {
    __shared__ __align__(16) float q_sh[DD];
    __shared__ __align__(16) float wpart[4][DD];
    __shared__ float s_sh[RR];
    __shared__ float e_sh[RR];
    __shared__ float red_sh[8];
    __shared__ float Mbc;

    const int c = blockIdx.x;
    const int t = threadIdx.x;
    const int lane = t & 31;
    const int wid = t >> 5;

    // --- prefetch this block's V tile into L2 (64KB: 2 x 128B lines/thread) ---
    {
        const char* vb = reinterpret_cast<const char*>(V) + (size_t)c * RR * DD * 4;
        l2_prefetch(vb + (size_t)t * 256);
        l2_prefetch(vb + (size_t)t * 256 + 128);
    }

    q_sh[t] = q[t];
    __syncthreads();

    const float4* q4 = reinterpret_cast<const float4*>(q_sh);
    const float4* K4 = reinterpret_cast<const float4*>(K) + (size_t)c * RR * 64;

    // --- s: 8 warps x 8 rows, one warp per row ---
    float4 qa = q4[lane], qb = q4[32 + lane];
#pragma unroll
    for (int k = 0; k < RR / 8; k++) {
        int r = wid * (RR / 8) + k;
        float4 ka = __ldcs(&K4[r * 64 + lane]);        // K read-once: evict-first
        float4 kb = __ldcs(&K4[r * 64 + 32 + lane]);
        float p = ka.x * qa.x + ka.y * qa.y + ka.z * qa.z + ka.w * qa.w
                + kb.x * qb.x + kb.y * qb.y + kb.z * qb.z + kb.w * qb.w;
#pragma unroll
        for (int o = 16; o; o >>= 1) p += __shfl_xor_sync(0xffffffffu, p, o);
        if (lane == 0) s_sh[r] = p;
    }
    __syncthreads();

    if (t < RR) g_s[c * RR + t] = s_sh[t];

    // --- chunk max M ---
    float m = (t < RR) ? s_sh[t] : NEG_INF;
#pragma unroll
    for (int o = 16; o; o >>= 1) m = fmaxf(m, __shfl_xor_sync(0xffffffffu, m, o));
    if (lane == 0) red_sh[wid] = m;
    __syncthreads();
    if (t == 0) {
        float mm = NEG_INF;
#pragma unroll
        for (int w = 0; w < 8; w++) mm = fmaxf(mm, red_sh[w]);
        Mbc = mm;
    }
    __syncthreads();
    const float M = Mbc;

    if (t < RR) e_sh[t] = __expf(s_sh[t] - M);
    __syncthreads();

    // --- U = sum e ---
    float uu = (t < RR) ? e_sh[t] : 0.f;
#pragma unroll
    for (int o = 16; o; o >>= 1) uu += __shfl_xor_sync(0xffffffffu, uu, o);
    __syncthreads();
    if (lane == 0) red_sh[wid] = uu;
    __syncthreads();
    if (t == 0) {
        float U = 0.f;
#pragma unroll
        for (int w = 0; w < 8; w++) U += red_sh[w];
        g_M[c] = M;
        g_U[c] = U;
    }

    // --- W[d] = sum_i e_i * V[i][d]   (V now largely L2-hot) ---
    const int grp = t >> 6;
    const int j = t & 63;
    const float4* V4 = reinterpret_cast<const float4*>(V) + (size_t)c * RR * 64;
    float4 acc = make_float4(0.f, 0.f, 0.f, 0.f);
#pragma unroll
    for (int i = grp; i < RR; i += 4) {
        float e = e_sh[i];
        float4 v = V4[i * 64 + j];
        acc.x += e * v.x; acc.y += e * v.y; acc.z += e * v.z; acc.w += e * v.w;
    }
    reinterpret_cast<float4*>(wpart[grp])[j] = acc;
    __syncthreads();
    float W = wpart[0][t] + wpart[1][t] + wpart[2][t] + wpart[3][t];
    g_W[(size_t)c * DD + t] = W;
}

// ============================================================
// Mid kernel: NSEG blocks. All-parallel scalar scans; block b
// does the register-resident segment W-scan for its chunks.
// ============================================================
__global__ __launch_bounds__(256) void k_mid() {
    __shared__ float Pm[CC];
    __shared__ float alsh[CC];
    __shared__ float gash[CC];
    __shared__ float As[CC];
    __shared__ float Bs[CC];

    const int b = blockIdx.x;
    const int t = threadIdx.x;

    float mv[4];
#pragma unroll
    for (int r = 0; r < 4; r++) {
        mv[r] = g_M[t + r * 256];
        Pm[t + r * 256] = mv[r];
    }
    __syncthreads();

    // inclusive prefix max (Hillis-Steele), 4 elems/thread
    float cm[4];
#pragma unroll
    for (int r = 0; r < 4; r++) cm[r] = mv[r];
    for (int off = 1; off < CC; off <<= 1) {
        float v[4];
#pragma unroll
        for (int r = 0; r < 4; r++) {
            int i = t + r * 256;
            v[r] = (i >= off) ? Pm[i - off] : NEG_INF;
        }
        __syncthreads();
#pragma unroll
        for (int r = 0; r < 4; r++) {
            cm[r] = fmaxf(cm[r], v[r]);
            Pm[t + r * 256] = cm[r];
        }
        __syncthreads();
    }

    float ca[4], cb[4];
#pragma unroll
    for (int r = 0; r < 4; r++) {
        int i = t + r * 256;
        float Minc = Pm[i];
        float Mp = (i == 0) ? NEG_INF : Pm[i - 1];
        float a = (i == 0) ? 0.f : __expf(Mp - Minc);
        float g = __expf(mv[r] - Minc);
        alsh[i] = a;
        gash[i] = g;
        ca[r] = a;
        cb[r] = g_U[i] * g;
        As[i] = ca[r];
        Bs[i] = cb[r];
        if (b == 0) g_Mp[i] = Mp;
    }
    __syncthreads();

    // inclusive pair scan for u
    for (int off = 1; off < CC; off <<= 1) {
        float va[4], vb[4];
#pragma unroll
        for (int r = 0; r < 4; r++) {
            int i = t + r * 256;
            if (i >= off) { va[r] = As[i - off]; vb[r] = Bs[i - off]; }
            else          { va[r] = 1.f;         vb[r] = 0.f; }
        }
        __syncthreads();
#pragma unroll
        for (int r = 0; r < 4; r++) {
            int i = t + r * 256;
            cb[r] = fmaf(vb[r], ca[r], cb[r]);
            ca[r] = va[r] * ca[r];
            As[i] = ca[r];
            Bs[i] = cb[r];
        }
        __syncthreads();
    }

    if (b == 0) {
#pragma unroll
        for (int r = 0; r < 4; r++) {
            int i = t + r * 256;
            g_Up[i] = (i == 0) ? 0.f : Bs[i - 1];   // exclusive, ref Mp_i
        }
    }

    // segment W-scan, register-resident
    const int j0 = b * SEGC;
    const float* Wsrc = g_W + (size_t)j0 * DD + t;
    float* Wdst = g_Wp + (size_t)j0 * DD + t;

    float wc[SEGC];
#pragma unroll
    for (int j = 0; j < SEGC; j++) wc[j] = Wsrc[(size_t)j * DD];

    float w = 0.f;
#pragma unroll
    for (int j = 0; j < SEGC; j++) {
        Wdst[(size_t)j * DD] = w;              // exclusive within segment, ref Mp_c
        w = fmaf(w, alsh[j0 + j], wc[j] * gash[j0 + j]);
    }
    g_seg[b * DD + t] = w;                     // ref Mp[(b+1)*SEGC]
}

// ============================================================
// Pass 2: rebuild per-row recurrence (all scans parallel),
// stream V -> out. Reverse chunk order for L2 reuse of V tail.
// V tile prefetched before the scan preamble.
// ============================================================
__global__ __launch_bounds__(256, 8) void k_pass2(const float* __restrict__ V,
                                                  float* __restrict__ out) {
    __shared__ float s_loc[RR], m_sh[RR];
    __shared__ float a_sh[RR], b_sh[RR];
    __shared__ float sA[RR], sB[RR];
    __shared__ float inv_sh[RR];

    const int c = (CC - 1) - blockIdx.x;
    const int t = threadIdx.x;

    // --- prefetch this block's V tile into L2 ---
    {
        const char* vb = reinterpret_cast<const char*>(V) + (size_t)c * RR * DD * 4;
        l2_prefetch(vb + (size_t)t * 256);
        l2_prefetch(vb + (size_t)t * 256 + 128);
    }

    const float Mp_c = g_Mp[c];
    const float Up_c = g_Up[c];

    if (t < RR) {
        float sv = g_s[c * RR + t];
        s_loc[t] = sv;
        m_sh[t] = sv;
    }
    __syncthreads();

    // inclusive prefix max over s within the chunk
    float cmx = (t < RR) ? m_sh[t] : NEG_INF;
#pragma unroll
    for (int off = 1; off < RR; off <<= 1) {
        float v = NEG_INF;
        if (t < RR && t >= off) v = m_sh[t - off];
        __syncthreads();
        if (t < RR) { cmx = fmaxf(cmx, v); m_sh[t] = cmx; }
        __syncthreads();
    }

    float cA = 1.f, cB = 0.f;
    if (t < RR) {
        float mi = fmaxf(m_sh[t], Mp_c);
        float mp = (t == 0) ? Mp_c : fmaxf(m_sh[t - 1], Mp_c);
        float a = __expf(mp - mi);            // exp(-inf - finite) = 0 : safe
        float bb = __expf(s_loc[t] - mi);
        a_sh[t] = a;
        b_sh[t] = bb;
        cA = a; cB = bb;
        sA[t] = a; sB[t] = bb;
    }
    __syncthreads();

    // inclusive pair scan: u_i = B_i + A_i * Up_c
#pragma unroll
    for (int off = 1; off < RR; off <<= 1) {
        float va = 1.f, vb = 0.f;
        if (t < RR && t >= off) { va = sA[t - off]; vb = sB[t - off]; }
        __syncthreads();
        if (t < RR) {
            cB = fmaf(vb, cA, cB);
            cA = va * cA;
            sA[t] = cA; sB[t] = cB;
        }
        __syncthreads();
    }
    if (t < RR) inv_sh[t] = 1.0f / fmaf(cA, Up_c, cB);
    __syncthreads();

    // seed: segment-local exclusive prefix + reconstructed carry
    const int seg = c / SEGC;
    float w = g_Wp[(size_t)c * DD + t];
    if (seg > 0) {
        float car = 0.f;
        for (int sb = 0; sb < seg; sb++) {
            float sc = (sb == 0) ? 0.f
                     : __expf(g_Mp[sb * SEGC] - g_Mp[(sb + 1) * SEGC]);
            car = fmaf(car, sc, g_seg[sb * DD + t]);
        }
        // car is ref Mp[seg*SEGC]; rescale to Mp_c
        w = fmaf(car, __expf(g_Mp[seg * SEGC] - Mp_c), w);
    }

    const float* Vb = V + (size_t)c * RR * DD + t;
    float* Ob = out + (size_t)c * RR * DD + t;

    float cur[8];
#pragma unroll
    for (int j = 0; j < 8; j++) cur[j] = Vb[(size_t)j * DD];

    for (int ib = 0; ib < RR; ib += 8) {
        float nxt[8];
#pragma unroll
        for (int j = 0; j < 8; j++)
            nxt[j] = (ib + 8 < RR) ? Vb[(size_t)(ib + 8 + j) * DD] : 0.f;
#pragma unroll
        for (int j = 0; j < 8; j++) {
            int i = ib + j;
            w = fmaf(w, a_sh[i], b_sh[i] * cur[j]);
            __stcs(&Ob[(size_t)i * DD], w * inv_sh[i]);   // write-once: stream
        }
#pragma unroll
        for (int j = 0; j < 8; j++) cur[j] = nxt[j];
    }
}

// ============================================================
extern "C" void kernel_launch(void* const* d_in, const int* in_sizes, int n_in,
                              void* d_out, int out_size) {
    const float* K = (const float*)d_in[0];
    const float* V = (const float*)d_in[1];
    const float* q = (const float*)d_in[2];
    float* out = (float*)d_out;

    k_pass1<<<CC, 256>>>(K, V, q);
    k_mid<<<NSEG, 256>>>();
    k_pass2<<<CC, 256>>>(V, out);
}